// round 12
// baseline (speedup 1.0000x reference)
#include <cuda_runtime.h>
#include <cstdint>

#define BATCHES 16
#define NPTS    65536
#define NSAMP   2048
#define CPB     8                  // CTAs per cluster (= per batch)
#define TPB     1024
#define PPT     8                  // points per thread
#define SLAB    (NPTS / CPB)       // 8192 points per CTA
#define SLAB_SHIFT 13              // log2(SLAB)

__device__ __forceinline__ uint32_t smem_u32(const void* p) {
    return (uint32_t)__cvta_generic_to_shared(p);
}
__device__ __forceinline__ void st_remote_u64(uint32_t laddr, uint32_t rank,
                                              unsigned long long v) {
    uint32_t raddr;
    asm volatile("mapa.shared::cluster.u32 %0, %1, %2;"
                 : "=r"(raddr) : "r"(laddr), "r"(rank));
    asm volatile("st.shared::cluster.u64 [%0], %1;"
                 :: "r"(raddr), "l"(v) : "memory");
}
__device__ __forceinline__ void st_remote_v4(uint32_t laddr, uint32_t rank,
                                             float x, float y, float z, float w) {
    uint32_t raddr;
    asm volatile("mapa.shared::cluster.u32 %0, %1, %2;"
                 : "=r"(raddr) : "r"(laddr), "r"(rank));
    asm volatile("st.shared::cluster.v4.f32 [%0], {%1, %2, %3, %4};"
                 :: "r"(raddr), "f"(x), "f"(y), "f"(z), "f"(w) : "memory");
}
// release-arrive on CTA `rank`'s mbarrier (orders prior cluster-space stores)
__device__ __forceinline__ void mbar_arrive_remote(uint32_t lmbar, uint32_t rank) {
    asm volatile(
        "{\n\t"
        ".reg .b32 r;\n\t"
        "mapa.shared::cluster.u32 r, %0, %1;\n\t"
        "mbarrier.arrive.release.cluster.shared::cluster.b64 _, [r];\n\t"
        "}"
        :: "r"(lmbar), "r"(rank) : "memory");
}
__device__ __forceinline__ void mbar_wait_parity(uint32_t mbar, uint32_t parity) {
    asm volatile(
        "{\n\t"
        ".reg .pred P;\n\t"
        "WL_%=:\n\t"
        "mbarrier.try_wait.parity.acquire.cluster.shared::cta.b64 P, [%0], %1, 0x989680;\n\t"
        "@P bra.uni WD_%=;\n\t"
        "bra.uni WL_%=;\n\t"
        "WD_%=:\n\t"
        "}"
        :: "r"(mbar), "r"(parity) : "memory");
}
__device__ __forceinline__ void cluster_barrier() {
    asm volatile("barrier.cluster.arrive.aligned;" ::: "memory");
    asm volatile("barrier.cluster.wait.aligned;"   ::: "memory");
}

__global__ void __launch_bounds__(TPB, 1) __cluster_dims__(CPB, 1, 1)
fps_cluster(const float* __restrict__ points, float* __restrict__ out)
{
    const int tid  = threadIdx.x;
    const int warp = tid >> 5;
    const int lane = tid & 31;
    uint32_t rank;
    asm("mov.u32 %0, %%cluster_ctarank;" : "=r"(rank));
    const int batch = blockIdx.x / CPB;
    const float* bp = points + (size_t)batch * NPTS * 3;

    __shared__ unsigned long long warp_keys[TPB / 32];
    __shared__ float4             warp_xyz[TPB / 32];
    __shared__ unsigned long long cta_keys[2][CPB];
    __shared__ float4             cta_xyz[2][CPB];
    __shared__ unsigned long long mbar[1];
    const uint32_t mbar_a = smem_u32(&mbar[0]);

    if (tid == 0) {
        asm volatile("mbarrier.init.shared.b64 [%0], %1;"
                     :: "r"(mbar_a), "r"(CPB) : "memory");
    }
    __syncthreads();

    // ---- register-resident points + min_dist (bit-proven R7 numeric core) ----
    float px[PPT], py[PPT], pz[PPT], md[PPT];
    const int base = (int)rank * SLAB + tid;      // owned indices ascend with k
    #pragma unroll
    for (int k = 0; k < PPT; k++) {
        int i = base + k * TPB;
        px[k] = __ldg(bp + 3 * i);
        py[k] = __ldg(bp + 3 * i + 1);
        pz[k] = __ldg(bp + 3 * i + 2);
        md[k] = 1e10f;
    }

    float cx = __ldg(bp), cy = __ldg(bp + 1), cz = __ldg(bp + 2);
    if (rank == 0 && tid == 0) out[batch * NSAMP] = 0.0f;

    cluster_barrier();   // mbarriers initialized cluster-wide; all CTAs resident

    for (int m = 1; m < NSAMP; m++) {
        // ---- distance update: validated d = fma(dz,dz, fma(dy,dy, dx*dx)) ----
        float vbest = -1.0f;
        #pragma unroll
        for (int k = 0; k < PPT; k++) {
            float dx = __fsub_rn(px[k], cx);
            float dy = __fsub_rn(py[k], cy);
            float dz = __fsub_rn(pz[k], cz);
            float d  = fmaf(dz, dz, fmaf(dy, dy, __fmul_rn(dx, dx)));
            float nm = fminf(md[k], d);
            md[k] = nm;
            vbest = fmaxf(vbest, nm);
        }
        // first occurrence: descending overwrite ends at SMALLEST matching k
        int bk = 0;
        #pragma unroll
        for (int k = PPT - 1; k >= 0; k--)
            if (md[k] == vbest) bk = k;
        const int bi = base + bk * TPB;

        // pack (monotone for v>=0): high=value bits, low=~idx.
        // u64 max == (value desc, idx asc) — validated comparator semantics.
        unsigned long long key =
            ((unsigned long long)__float_as_uint(vbest) << 32)
            | (unsigned int)(~(unsigned int)bi);
        float wx = px[bk], wy = py[bk], wz = pz[bk];   // candidate coords ride along

        // ---- warp reduce: (key,x,y,z) tuple ----
        #pragma unroll
        for (int off = 16; off > 0; off >>= 1) {
            unsigned long long ok = __shfl_xor_sync(0xffffffffu, key, off);
            float ox = __shfl_xor_sync(0xffffffffu, wx, off);
            float oy = __shfl_xor_sync(0xffffffffu, wy, off);
            float oz = __shfl_xor_sync(0xffffffffu, wz, off);
            if (ok > key) { key = ok; wx = ox; wy = oy; wz = oz; }
        }
        if (lane == 0) {
            warp_keys[warp] = key;
            warp_xyz[warp]  = make_float4(wx, wy, wz, 0.0f);
        }
        __syncthreads();

        // ---- block reduce (warp 0) + DSMEM delivery of (key, xyz) ----
        if (warp == 0) {
            key = warp_keys[lane];
            float4 t = warp_xyz[lane];
            wx = t.x; wy = t.y; wz = t.z;
            #pragma unroll
            for (int off = 16; off > 0; off >>= 1) {
                unsigned long long ok = __shfl_xor_sync(0xffffffffu, key, off);
                float ox = __shfl_xor_sync(0xffffffffu, wx, off);
                float oy = __shfl_xor_sync(0xffffffffu, wy, off);
                float oz = __shfl_xor_sync(0xffffffffu, wz, off);
                if (ok > key) { key = ok; wx = ox; wy = oy; wz = oz; }
            }
            if (lane < CPB) {
                st_remote_u64(smem_u32(&cta_keys[m & 1][rank]), (uint32_t)lane, key);
                st_remote_v4(smem_u32(&cta_xyz[m & 1][rank]), (uint32_t)lane,
                             wx, wy, wz, 0.0f);
                mbar_arrive_remote(mbar_a, (uint32_t)lane);
            }
        }

        // acquire-wait: all 8 CTAs' (key,xyz) for iteration m are in local smem
        mbar_wait_parity(mbar_a, (uint32_t)((m - 1) & 1));

        // ---- cheap final reduce: one key per lane group, 3 shfl rounds ----
        unsigned long long k8 = cta_keys[m & 1][lane & 7];
        #pragma unroll
        for (int off = 4; off > 0; off >>= 1) {
            unsigned long long ok = __shfl_xor_sync(0xffffffffu, k8, off);
            if (ok > k8) k8 = ok;
        }
        const int widx = (int)(~(unsigned int)k8);
        const int wr   = widx >> SLAB_SHIFT;          // winning rank (slab owner)
        float4 c = cta_xyz[m & 1][wr];                // broadcast LDS — no global load
        cx = c.x; cy = c.y; cz = c.z;

        if (rank == 0 && tid == 0) out[batch * NSAMP + m] = (float)widx;
        // slot reuse (m+2) safe: writing m+2 requires passing wait(m+1),
        // which requires every CTA's m+1 arrival, which follows their m reads.
    }
}

extern "C" void kernel_launch(void* const* d_in, const int* in_sizes, int n_in,
                              void* d_out, int out_size) {
    const float* points = (const float*)d_in[0];
    float* out = (float*)d_out;

    cudaLaunchConfig_t cfg = {};
    cfg.gridDim  = dim3(BATCHES * CPB, 1, 1);
    cfg.blockDim = dim3(TPB, 1, 1);
    cfg.dynamicSmemBytes = 0;
    cfg.stream = 0;

    cudaLaunchAttribute attrs[1];
    attrs[0].id = cudaLaunchAttributeClusterDimension;
    attrs[0].val.clusterDim.x = CPB;
    attrs[0].val.clusterDim.y = 1;
    attrs[0].val.clusterDim.z = 1;
    cfg.attrs = attrs;
    cfg.numAttrs = 1;

    cudaLaunchKernelEx(&cfg, fps_cluster, points, out);
}

// round 13
// speedup vs baseline: 1.8705x; 1.8705x over previous
#include <cuda_runtime.h>
#include <cstdint>

#define BATCHES 16
#define NPTS    65536
#define NSAMP   2048
#define CPB     8                  // CTAs per cluster (= per batch)
#define TPB     512
#define NWARPS  (TPB / 32)         // 16
#define PPT     16                 // points per thread
#define SLAB    (NPTS / CPB)       // 8192 = TPB * PPT
#define SLAB_SHIFT 13              // log2(SLAB)

__device__ __forceinline__ uint32_t smem_u32(const void* p) {
    return (uint32_t)__cvta_generic_to_shared(p);
}
__device__ __forceinline__ void st_remote_v2(uint32_t laddr, uint32_t rank,
                                             uint32_t a, uint32_t b) {
    uint32_t raddr;
    asm volatile("mapa.shared::cluster.u32 %0, %1, %2;"
                 : "=r"(raddr) : "r"(laddr), "r"(rank));
    asm volatile("st.shared::cluster.v2.b32 [%0], {%1, %2};"
                 :: "r"(raddr), "r"(a), "r"(b) : "memory");
}
__device__ __forceinline__ void st_remote_v4(uint32_t laddr, uint32_t rank,
                                             float x, float y, float z, float w) {
    uint32_t raddr;
    asm volatile("mapa.shared::cluster.u32 %0, %1, %2;"
                 : "=r"(raddr) : "r"(laddr), "r"(rank));
    asm volatile("st.shared::cluster.v4.f32 [%0], {%1, %2, %3, %4};"
                 :: "r"(raddr), "f"(x), "f"(y), "f"(z), "f"(w) : "memory");
}
__device__ __forceinline__ void cluster_barrier() {
    asm volatile("barrier.cluster.arrive.aligned;" ::: "memory");
    asm volatile("barrier.cluster.wait.aligned;"   ::: "memory");
}

__global__ void __launch_bounds__(TPB, 1) __cluster_dims__(CPB, 1, 1)
fps_cluster(const float* __restrict__ points, float* __restrict__ out)
{
    const int tid  = threadIdx.x;
    const int warp = tid >> 5;
    const int lane = tid & 31;
    uint32_t rank;
    asm("mov.u32 %0, %%cluster_ctarank;" : "=r"(rank));
    const int batch = blockIdx.x / CPB;
    const float* bp = points + (size_t)batch * NPTS * 3;

    __shared__ uint2  warp_pair[NWARPS];     // {valbits, idx} per warp
    __shared__ float4 warp_xyz[NWARPS];
    __shared__ uint2  cta_pair[2][CPB];      // {valbits, idx} per CTA, dbl-buffered
    __shared__ float4 cta_xyz[2][CPB];

    // ---- register-resident points + min_dist (bit-proven numeric core) ----
    float px[PPT], py[PPT], pz[PPT], md[PPT];
    const int base = (int)rank * SLAB + tid;      // owned indices ascend with k
    #pragma unroll
    for (int k = 0; k < PPT; k++) {
        int i = base + k * TPB;
        px[k] = __ldg(bp + 3 * i);
        py[k] = __ldg(bp + 3 * i + 1);
        pz[k] = __ldg(bp + 3 * i + 2);
        md[k] = 1e10f;
    }

    float cx = __ldg(bp), cy = __ldg(bp + 1), cz = __ldg(bp + 2);
    if (rank == 0 && tid == 0) out[batch * NSAMP] = 0.0f;

    cluster_barrier();   // all cluster CTAs resident before DSMEM traffic

    for (int m = 1; m < NSAMP; m++) {
        // ---- distance update: validated d = fma(dz,dz, fma(dy,dy, dx*dx)) ----
        float vbest = -1.0f;
        #pragma unroll
        for (int k = 0; k < PPT; k++) {
            float dx = __fsub_rn(px[k], cx);
            float dy = __fsub_rn(py[k], cy);
            float dz = __fsub_rn(pz[k], cz);
            float d  = fmaf(dz, dz, fmaf(dy, dy, __fmul_rn(dx, dx)));
            float nm = fminf(md[k], d);
            md[k] = nm;
            vbest = fmaxf(vbest, nm);
        }
        // first occurrence: descending overwrite ends at SMALLEST matching k
        int bk = 0;
        #pragma unroll
        for (int k = PPT - 1; k >= 0; k--)
            if (md[k] == vbest) bk = k;
        const uint32_t bi = (uint32_t)(base + bk * TPB);

        // ---- warp argmax via REDUX (md >= 0 => u32 order == float order) ----
        const uint32_t vbits = __float_as_uint(vbest);
        const uint32_t wv = __reduce_max_sync(0xffffffffu, vbits);
        const uint32_t wi = __reduce_min_sync(0xffffffffu,
                                (vbits == wv) ? bi : 0xffffffffu);
        if (bi == wi) {                        // exactly one lane (indices unique)
            warp_pair[warp] = make_uint2(wv, wi);
            warp_xyz[warp]  = make_float4(px[bk], py[bk], pz[bk], 0.0f);
        }
        __syncthreads();

        // ---- block argmax (warp 0) + DSMEM delivery of {val,idx} + xyz ----
        if (warp == 0) {
            uint2 p = warp_pair[lane & (NWARPS - 1)];   // dups harmless for max/min
            const uint32_t bv  = __reduce_max_sync(0xffffffffu, p.x);
            const uint32_t bix = __reduce_min_sync(0xffffffffu,
                                    (p.x == bv) ? p.y : 0xffffffffu);
            if (lane < CPB) {
                const int wwarp = (int)((bix & (TPB - 1)) >> 5);  // winner's warp
                float4 t = warp_xyz[wwarp];                       // uniform LDS
                st_remote_v2(smem_u32(&cta_pair[m & 1][rank]), (uint32_t)lane,
                             bv, bix);
                st_remote_v4(smem_u32(&cta_xyz[m & 1][rank]), (uint32_t)lane,
                             t.x, t.y, t.z, 0.0f);
            }
        }

        // HW release/acquire across the cluster (best-measured sync, R10)
        cluster_barrier();

        // ---- cluster argmax: 8 B LDS/thread + 2 REDUX ----
        uint2 q = cta_pair[m & 1][lane & (CPB - 1)];
        const uint32_t gv = __reduce_max_sync(0xffffffffu, q.x);
        const uint32_t gi = __reduce_min_sync(0xffffffffu,
                                (q.x == gv) ? q.y : 0xffffffffu);
        const int widx = (int)gi;
        const int wr   = widx >> SLAB_SHIFT;         // winning rank (slab owner)
        float4 c = cta_xyz[m & 1][wr];               // uniform LDS broadcast
        cx = c.x; cy = c.y; cz = c.z;

        if (rank == 0 && tid == 0) out[batch * NSAMP + m] = (float)widx;
        // warp_pair reuse (m+1): writes occur only after this thread passes
        // cluster wait(m), which requires warp0's arrive(m), which follows
        // warp0's reads(m). cta_* slot reuse (m+2) is separated by the
        // m+1 cluster barrier by the same transitive argument.
    }
}

extern "C" void kernel_launch(void* const* d_in, const int* in_sizes, int n_in,
                              void* d_out, int out_size) {
    const float* points = (const float*)d_in[0];
    float* out = (float*)d_out;

    cudaLaunchConfig_t cfg = {};
    cfg.gridDim  = dim3(BATCHES * CPB, 1, 1);
    cfg.blockDim = dim3(TPB, 1, 1);
    cfg.dynamicSmemBytes = 0;
    cfg.stream = 0;

    cudaLaunchAttribute attrs[1];
    attrs[0].id = cudaLaunchAttributeClusterDimension;
    attrs[0].val.clusterDim.x = CPB;
    attrs[0].val.clusterDim.y = 1;
    attrs[0].val.clusterDim.z = 1;
    cfg.attrs = attrs;
    cfg.numAttrs = 1;

    cudaLaunchKernelEx(&cfg, fps_cluster, points, out);
}